// round 4
// baseline (speedup 1.0000x reference)
#include <cuda_runtime.h>

#define N_NODES 50000
#define N_EDGES 800000
#define ED 54
#define HID 64

// Scratch (device globals: allocation-free rule)
__device__ float g_agg[N_NODES * HID];   // layer-1 aggregation, 12.8 MB
__device__ float g_p[N_NODES * 56];      // p[0..53], q at [54], pad to 56
__device__ int   g_ei[2 * N_EDGES];      // normalized int32 indices
__device__ int   g_idx_is64;             // dtype flag

// ---------------- K0a: detect edge_index dtype ----------------
// int64 values < 2^31 -> int32 view has 0 in every odd word. Sample 64 odd words.
__global__ void k0a_detect(const int* __restrict__ ei_raw) {
    int lane = threadIdx.x;                       // 32 threads
    int nz = 0;
    #pragma unroll
    for (int r = 0; r < 2; r++) {
        int i = lane + r * 32;                    // sample 64 entries
        if (ei_raw[(2 * i * 9973 % (2 * N_EDGES)) | 1] != 0) nz = 1;
    }
    #pragma unroll
    for (int off = 16; off; off >>= 1) nz |= __shfl_down_sync(0xffffffffu, nz, off);
    if (lane == 0) g_idx_is64 = (nz == 0);
}

// ---------------- K0b: normalize indices to int32 (clamped: never OOB) ----------------
__global__ void k0b_convert(const void* __restrict__ ei_raw) {
    int i = blockIdx.x * blockDim.x + threadIdx.x;   // 6250*256 = 1.6M exactly
    long long v;
    if (g_idx_is64)
        v = ((const long long*)ei_raw)[i];
    else
        v = ((const int*)ei_raw)[i];
    if (v < 0) v = 0;
    if (v >= N_NODES) v = N_NODES - 1;
    g_ei[i] = (int)v;
}

// ---------------- zero agg ----------------
__global__ void zero_agg_kernel() {
    int i = blockIdx.x * blockDim.x + threadIdx.x;   // 3125*256 = 800000 float4s exactly
    float4 z = {0.f, 0.f, 0.f, 0.f};
    reinterpret_cast<float4*>(g_agg)[i] = z;
}

// ---------------- K1: layer-1 edge GEMM + scatter ----------------
// C[128 edges, 64] = sum_i x_src[e,i] * (ea[e,:] @ w_e1[:, i*64 + o]) ; red-add into g_agg[dst]
// Static smem (<48KB): sB 54*64 (one i-slice) | sA 128*55 | sXj 512 | sBe1 256 | sDst 128
__global__ __launch_bounds__(128) void k1_edge_layer1(
    const float* __restrict__ x,
    const float* __restrict__ ea, const float* __restrict__ w_e1,
    const float* __restrict__ b_e1)
{
    __shared__ float sB[54 * 64];      // w_e1 slice for current i
    __shared__ float sA[128 * 55];     // edge_attr tile, stride 55 (conflict-free)
    __shared__ float sXj[128 * 4];
    __shared__ float sBe1[256];
    __shared__ int   sDst[128];

    const int tid = threadIdx.x;
    const int e0  = blockIdx.x * 128;  // 800000 = 6250*128 exactly

    // stage edge_attr tile (contiguous) into padded rows
    {
        const float* eaBlk = ea + (size_t)e0 * ED;
        for (int idx = tid; idx < 128 * ED; idx += 128) {
            int e = idx / ED, k = idx - e * ED;
            sA[e * 55 + k] = eaBlk[idx];
        }
    }
    // gather x[src], stage dst
    {
        int src = g_ei[e0 + tid];
        sDst[tid] = g_ei[N_EDGES + e0 + tid];
        float4 xv = *reinterpret_cast<const float4*>(x + (size_t)src * 4);
        sXj[tid * 4 + 0] = xv.x; sXj[tid * 4 + 1] = xv.y;
        sXj[tid * 4 + 2] = xv.z; sXj[tid * 4 + 3] = xv.w;
    }
    for (int idx = tid; idx < 256; idx += 128) sBe1[idx] = b_e1[idx];

    const int tr = tid >> 3;      // 0..15 -> edges tr*8..tr*8+7
    const int tc = tid & 7;       // 0..7  -> cols  tc*8..tc*8+7

    float C[8][8];
    #pragma unroll
    for (int e = 0; e < 8; e++)
        #pragma unroll
        for (int o = 0; o < 8; o++) C[e][o] = 0.f;

    const float* sArow = sA + tr * 8 * 55;

    for (int i = 0; i < 4; i++) {
        __syncthreads();
        // stage w_e1 i-slice: sB[k*64+o] = w_e1[k*256 + i*64 + o]
        for (int idx = tid; idx < 54 * 64; idx += 128) {
            int k = idx >> 6, o = idx & 63;
            sB[idx] = w_e1[k * 256 + i * 64 + o];
        }
        __syncthreads();

        float xji[8];
        #pragma unroll
        for (int e = 0; e < 8; e++) xji[e] = sXj[(tr * 8 + e) * 4 + i];
        const float* Bi = sB + tc * 8;
        #pragma unroll 3
        for (int k = 0; k < 54; k++) {
            float4 b0 = *reinterpret_cast<const float4*>(Bi + k * 64);
            float4 b1 = *reinterpret_cast<const float4*>(Bi + k * 64 + 4);
            #pragma unroll
            for (int e = 0; e < 8; e++) {
                float a = sArow[e * 55 + k] * xji[e];
                C[e][0] += a * b0.x; C[e][1] += a * b0.y;
                C[e][2] += a * b0.z; C[e][3] += a * b0.w;
                C[e][4] += a * b1.x; C[e][5] += a * b1.y;
                C[e][6] += a * b1.z; C[e][7] += a * b1.w;
            }
        }
    }

    // epilogue: add x_j-contracted bias, vector red into g_agg[dst]
    #pragma unroll
    for (int e = 0; e < 8; e++) {
        int el = tr * 8 + e;
        float xv0 = sXj[el * 4 + 0], xv1 = sXj[el * 4 + 1];
        float xv2 = sXj[el * 4 + 2], xv3 = sXj[el * 4 + 3];
        int d = sDst[el];
        float* dp = g_agg + (size_t)d * HID + tc * 8;
        float v[8];
        #pragma unroll
        for (int o = 0; o < 8; o++) {
            int col = tc * 8 + o;
            v[o] = C[e][o] + xv0 * sBe1[col] + xv1 * sBe1[64 + col]
                           + xv2 * sBe1[128 + col] + xv3 * sBe1[192 + col];
        }
        asm volatile("red.global.add.v4.f32 [%0], {%1,%2,%3,%4};"
                     :: "l"(dp), "f"(v[0]), "f"(v[1]), "f"(v[2]), "f"(v[3]) : "memory");
        asm volatile("red.global.add.v4.f32 [%0], {%1,%2,%3,%4};"
                     :: "l"(dp + 4), "f"(v[4]), "f"(v[5]), "f"(v[6]), "f"(v[7]) : "memory");
    }
}

// ---------------- K2: node update; h = relu(agg + x@root1 + b1); emit p,q and out-init ----------------
__global__ __launch_bounds__(256) void k2_node(
    const float* __restrict__ x, const float* __restrict__ root1,
    const float* __restrict__ bias1, const float* __restrict__ w_e2,
    const float* __restrict__ b_e2, const float* __restrict__ root2,
    const float* __restrict__ bias2, float* __restrict__ out)
{
    __shared__ float sR1[256], sB1[64], sR2[64];
    __shared__ float sW2[55 * 65];      // row 54 = b_e2; stride 65 -> conflict-free
    __shared__ float sH[8][64];

    const int tid = threadIdx.x;
    for (int idx = tid; idx < 55 * 64; idx += 256) {
        int k = idx >> 6, o = idx & 63;
        sW2[k * 65 + o] = (k < 54) ? w_e2[k * 64 + o] : b_e2[o];
    }
    if (tid < 256) sR1[tid] = root1[tid];
    if (tid < 64) { sB1[tid] = bias1[tid]; sR2[tid] = root2[tid]; }
    __syncthreads();

    const int wid = tid >> 5, lane = tid & 31;
    const int n = blockIdx.x * 8 + wid;
    if (n >= N_NODES) return;

    const float* aggr = g_agg + (size_t)n * HID;
    float x0 = x[n * 4 + 0], x1 = x[n * 4 + 1], x2 = x[n * 4 + 2], x3 = x[n * 4 + 3];
    int l2 = lane + 32;
    float h0 = aggr[lane] + x0 * sR1[lane] + x1 * sR1[64 + lane]
             + x2 * sR1[128 + lane] + x3 * sR1[192 + lane] + sB1[lane];
    float h1 = aggr[l2] + x0 * sR1[l2] + x1 * sR1[64 + l2]
             + x2 * sR1[128 + l2] + x3 * sR1[192 + l2] + sB1[l2];
    h0 = fmaxf(h0, 0.f); h1 = fmaxf(h1, 0.f);
    sH[wid][lane] = h0; sH[wid][l2] = h1;
    __syncwarp();

    float* pn = g_p + (size_t)n * 56;
    {
        float acc = 0.f;
        #pragma unroll
        for (int o = 0; o < 64; o++) acc += sW2[lane * 65 + o] * sH[wid][o];
        pn[lane] = acc;
    }
    if (l2 < 55) {
        float acc = 0.f;
        #pragma unroll
        for (int o = 0; o < 64; o++) acc += sW2[l2 * 65 + o] * sH[wid][o];
        pn[l2] = acc;
    }
    // out init = h @ root2 + bias2
    float t = h0 * sR2[lane] + h1 * sR2[l2];
    #pragma unroll
    for (int off = 16; off; off >>= 1) t += __shfl_down_sync(0xffffffffu, t, off);
    if (lane == 0) out[n] = t + bias2[0];
}

// ---------------- K3: layer-2 edges: out[dst] += ea[e].p[src] + q[src] ----------------
__global__ __launch_bounds__(256) void k3_edge_layer2(
    const float* __restrict__ ea, float* __restrict__ out)
{
    const int tid = threadIdx.x, wid = tid >> 5, lane = tid & 31;
    const int e = blockIdx.x * 8 + wid;
    if (e >= N_EDGES) return;
    int src = g_ei[e], dst = g_ei[N_EDGES + e];
    const float* ear = ea + (size_t)e * ED;
    const float* pr  = g_p + (size_t)src * 56;
    float t = ear[lane] * pr[lane];
    int l2 = lane + 32;
    if (l2 < ED) t += ear[l2] * pr[l2];
    if (lane == 0) t += pr[54];                 // q term (implicit ea=1)
    #pragma unroll
    for (int off = 16; off; off >>= 1) t += __shfl_down_sync(0xffffffffu, t, off);
    if (lane == 0) atomicAdd(out + dst, t);
}

// ---------------- launch ----------------
extern "C" void kernel_launch(void* const* d_in, const int* in_sizes, int n_in,
                              void* d_out, int out_size) {
    const float* x     = (const float*)d_in[0];
    const void*  ei    = d_in[1];
    const float* ea    = (const float*)d_in[2];
    const float* w_e1  = (const float*)d_in[3];
    const float* b_e1  = (const float*)d_in[4];
    const float* root1 = (const float*)d_in[5];
    const float* bias1 = (const float*)d_in[6];
    const float* w_e2  = (const float*)d_in[7];
    const float* b_e2  = (const float*)d_in[8];
    const float* root2 = (const float*)d_in[9];
    const float* bias2 = (const float*)d_in[10];
    float* out = (float*)d_out;

    k0a_detect<<<1, 32>>>((const int*)ei);
    k0b_convert<<<6250, 256>>>(ei);
    zero_agg_kernel<<<3125, 256>>>();
    k1_edge_layer1<<<N_EDGES / 128, 128>>>(x, ea, w_e1, b_e1);
    k2_node<<<(N_NODES + 7) / 8, 256>>>(x, root1, bias1, w_e2, b_e2, root2, bias2, out);
    k3_edge_layer2<<<N_EDGES / 8, 256>>>(ea, out);
}

// round 6
// speedup vs baseline: 1.2460x; 1.2460x over previous
#include <cuda_runtime.h>
#include <cstdint>

#define N_NODES 50000
#define N_EDGES 800000
#define ED 54
#define HID 64

// ---------------- scratch (device globals: allocation-free rule) ----------------
__device__ float g_agg[N_NODES * HID];   // layer-1 aggregation, 12.8 MB
__device__ float g_p[N_NODES * 56];      // p[0..53], q at [54], pad to 56
__device__ int   g_ei[2 * N_EDGES];      // normalized int32 indices
__device__ int   g_idx_is64;             // dtype flag

__device__ __forceinline__ uint32_t f2tf32(float f) {
    uint32_t r;
    asm("cvt.rna.tf32.f32 %0, %1;" : "=r"(r) : "f"(f));
    return r;
}

// ---------------- K0a: detect edge_index dtype ----------------
__global__ void k0a_detect(const int* __restrict__ ei_raw) {
    int lane = threadIdx.x;
    int nz = 0;
    #pragma unroll
    for (int r = 0; r < 2; r++) {
        int i = lane + r * 32;
        if (ei_raw[(2 * i * 9973 % (2 * N_EDGES)) | 1] != 0) nz = 1;
    }
    #pragma unroll
    for (int off = 16; off; off >>= 1) nz |= __shfl_down_sync(0xffffffffu, nz, off);
    if (lane == 0) g_idx_is64 = (nz == 0);
}

// ---------------- K0b: normalize indices to int32 (clamped: never OOB) ----------------
__global__ void k0b_convert(const void* __restrict__ ei_raw) {
    int i = blockIdx.x * blockDim.x + threadIdx.x;   // 6250*256 = 1.6M exactly
    long long v;
    if (g_idx_is64) v = ((const long long*)ei_raw)[i];
    else            v = ((const int*)ei_raw)[i];
    if (v < 0) v = 0;
    if (v >= N_NODES) v = N_NODES - 1;
    g_ei[i] = (int)v;
}

// ---------------- zero agg ----------------
__global__ void zero_agg_kernel() {
    int i = blockIdx.x * blockDim.x + threadIdx.x;   // 3125*256 = 800000 float4s
    float4 z = {0.f, 0.f, 0.f, 0.f};
    reinterpret_cast<float4*>(g_agg)[i] = z;
}

// ---------------- K1: layer-1 edge GEMM via mma.sync tf32 + scatter ----------------
// Per 128-edge tile:  D[128,64] = A[128,224] @ B[224,64]
//   A[e, i*56+k] = ea[e,k]*x_i (k<54) | x_i (k==54) | 0
//   B[i*56+k, o] = w_e1[k, i*64+o] (k<54) | b_e1[i*64+o] (k==54) | 0
// Phased over i (4 phases of K=56 = 7 k8-steps). Warp w owns edges [w*32, w*32+32).
#define SA_STRIDE 136   // (k*136+e) mod 32 = (8k+e) mod 32 -> conflict-free frag loads & staging
#define SB_STRIDE 72    // (k*72+o)  mod 32 = (8k+o) mod 32 -> conflict-free frag loads

__global__ __launch_bounds__(128) void k1_mma(
    const float* __restrict__ x, const float* __restrict__ ea,
    const float* __restrict__ w_e1, const float* __restrict__ b_e1)
{
    __shared__ uint32_t sA[56 * SA_STRIDE];   // 30464 B, tf32 bits, [k][e]
    __shared__ uint32_t sB[56 * SB_STRIDE];   // 16128 B, tf32 bits, [k][o]
    __shared__ int sDst[128];

    const int tid  = threadIdx.x;
    const int wid  = tid >> 5;
    const int lane = tid & 31;
    const int g    = lane >> 2;     // group 0..7
    const int tg   = lane & 3;      // thread-in-group 0..3
    const int wbase = wid * 32;
    const int e0 = blockIdx.x * 128;            // 6250*128 = 800000

    // per-thread edge data
    const int eg = e0 + tid;
    float ar[ED];
    {
        const float2* e2 = reinterpret_cast<const float2*>(ea + (size_t)eg * ED);
        #pragma unroll
        for (int j = 0; j < 27; j++) { float2 v = e2[j]; ar[2*j] = v.x; ar[2*j+1] = v.y; }
    }
    const int src = g_ei[eg];
    sDst[tid] = g_ei[N_EDGES + eg];
    float4 xv = *reinterpret_cast<const float4*>(x + (size_t)src * 4);
    float xr[4] = {xv.x, xv.y, xv.z, xv.w};

    float acc[2][8][4];
    #pragma unroll
    for (int mi = 0; mi < 2; mi++)
        #pragma unroll
        for (int n = 0; n < 8; n++)
            #pragma unroll
            for (int c = 0; c < 4; c++) acc[mi][n][c] = 0.f;

    for (int p = 0; p < 4; p++) {
        __syncthreads();   // previous phase's mma reads done before restage
        // stage A column e=tid (conflict-free: banks (8k+e)%32)
        #pragma unroll
        for (int k = 0; k < ED; k++)
            sA[k * SA_STRIDE + tid] = f2tf32(ar[k] * xr[p]);
        sA[54 * SA_STRIDE + tid] = f2tf32(xr[p]);
        sA[55 * SA_STRIDE + tid] = 0u;
        // stage B slice (cooperative, 28 elems/thread)
        for (int idx = tid; idx < 56 * 64; idx += 128) {
            int k = idx >> 6, o = idx & 63;
            float v = 0.f;
            if (k < 54)       v = w_e1[k * 256 + p * 64 + o];
            else if (k == 54) v = b_e1[p * 64 + o];
            sB[k * SB_STRIDE + o] = f2tf32(v);
        }
        __syncthreads();

        #pragma unroll
        for (int kb = 0; kb < 7; kb++) {
            const uint32_t* rowA0 = sA + (kb * 8 + tg) * SA_STRIDE;
            const uint32_t* rowA4 = rowA0 + 4 * SA_STRIDE;
            const uint32_t* rowB0 = sB + (kb * 8 + tg) * SB_STRIDE + g;
            const uint32_t* rowB4 = rowB0 + 4 * SB_STRIDE;
            uint32_t b0[8], b1[8];
            #pragma unroll
            for (int n = 0; n < 8; n++) { b0[n] = rowB0[n * 8]; b1[n] = rowB4[n * 8]; }
            #pragma unroll
            for (int mi = 0; mi < 2; mi++) {
                int be = wbase + mi * 16 + g;
                uint32_t a0 = rowA0[be], a1 = rowA0[be + 8];
                uint32_t a2 = rowA4[be], a3 = rowA4[be + 8];
                #pragma unroll
                for (int n = 0; n < 8; n++) {
                    asm volatile(
                        "mma.sync.aligned.m16n8k8.row.col.f32.tf32.tf32.f32 "
                        "{%0,%1,%2,%3}, {%4,%5,%6,%7}, {%8,%9}, {%0,%1,%2,%3};"
                        : "+f"(acc[mi][n][0]), "+f"(acc[mi][n][1]),
                          "+f"(acc[mi][n][2]), "+f"(acc[mi][n][3])
                        : "r"(a0), "r"(a1), "r"(a2), "r"(a3), "r"(b0[n]), "r"(b1[n]));
                }
            }
        }
    }

    // epilogue: scatter fragments. c0,c1 -> row g; c2,c3 -> row g+8. cols = n*8 + tg*2 +{0,1}
    #pragma unroll
    for (int mi = 0; mi < 2; mi++) {
        int el = wbase + mi * 16 + g;
        int dA = sDst[el], dB = sDst[el + 8];
        float* pA = g_agg + (size_t)dA * HID + tg * 2;
        float* pB = g_agg + (size_t)dB * HID + tg * 2;
        #pragma unroll
        for (int n = 0; n < 8; n++) {
            asm volatile("red.global.add.v2.f32 [%0], {%1,%2};"
                         :: "l"(pA + n * 8), "f"(acc[mi][n][0]), "f"(acc[mi][n][1]) : "memory");
            asm volatile("red.global.add.v2.f32 [%0], {%1,%2};"
                         :: "l"(pB + n * 8), "f"(acc[mi][n][2]), "f"(acc[mi][n][3]) : "memory");
        }
    }
}

// ---------------- K2: node update; h = relu(agg + x@root1 + b1); emit p,q and out-init ----------------
__global__ __launch_bounds__(256) void k2_node(
    const float* __restrict__ x, const float* __restrict__ root1,
    const float* __restrict__ bias1, const float* __restrict__ w_e2,
    const float* __restrict__ b_e2, const float* __restrict__ root2,
    const float* __restrict__ bias2, float* __restrict__ out)
{
    __shared__ float sR1[256], sB1[64], sR2[64];
    __shared__ float sW2[55 * 65];      // row 54 = b_e2; stride 65 -> conflict-free
    __shared__ float sH[8][64];

    const int tid = threadIdx.x;
    for (int idx = tid; idx < 55 * 64; idx += 256) {
        int k = idx >> 6, o = idx & 63;
        sW2[k * 65 + o] = (k < 54) ? w_e2[k * 64 + o] : b_e2[o];
    }
    if (tid < 256) sR1[tid] = root1[tid];
    if (tid < 64) { sB1[tid] = bias1[tid]; sR2[tid] = root2[tid]; }
    __syncthreads();

    const int wid = tid >> 5, lane = tid & 31;
    const int n = blockIdx.x * 8 + wid;
    if (n >= N_NODES) return;

    const float* aggr = g_agg + (size_t)n * HID;
    float x0 = x[n * 4 + 0], x1 = x[n * 4 + 1], x2 = x[n * 4 + 2], x3 = x[n * 4 + 3];
    int l2 = lane + 32;
    float h0 = aggr[lane] + x0 * sR1[lane] + x1 * sR1[64 + lane]
             + x2 * sR1[128 + lane] + x3 * sR1[192 + lane] + sB1[lane];
    float h1 = aggr[l2] + x0 * sR1[l2] + x1 * sR1[64 + l2]
             + x2 * sR1[128 + l2] + x3 * sR1[192 + l2] + sB1[l2];
    h0 = fmaxf(h0, 0.f); h1 = fmaxf(h1, 0.f);
    sH[wid][lane] = h0; sH[wid][l2] = h1;
    __syncwarp();

    float* pn = g_p + (size_t)n * 56;
    {
        float acc = 0.f;
        #pragma unroll
        for (int o = 0; o < 64; o++) acc += sW2[lane * 65 + o] * sH[wid][o];
        pn[lane] = acc;
    }
    if (l2 < 55) {
        float acc = 0.f;
        #pragma unroll
        for (int o = 0; o < 64; o++) acc += sW2[l2 * 65 + o] * sH[wid][o];
        pn[l2] = acc;
    }
    float t = h0 * sR2[lane] + h1 * sR2[l2];
    #pragma unroll
    for (int off = 16; off; off >>= 1) t += __shfl_down_sync(0xffffffffu, t, off);
    if (lane == 0) out[n] = t + bias2[0];
}

// ---------------- K3: layer-2 edges: out[dst] += ea[e].p[src] + q[src] ----------------
__global__ __launch_bounds__(256) void k3_edge_layer2(
    const float* __restrict__ ea, float* __restrict__ out)
{
    const int tid = threadIdx.x, wid = tid >> 5, lane = tid & 31;
    const int e = blockIdx.x * 8 + wid;
    if (e >= N_EDGES) return;
    int src = g_ei[e], dst = g_ei[N_EDGES + e];
    const float* ear = ea + (size_t)e * ED;
    const float* pr  = g_p + (size_t)src * 56;
    float t = ear[lane] * pr[lane];
    int l2 = lane + 32;
    if (l2 < ED) t += ear[l2] * pr[l2];
    if (lane == 0) t += pr[54];                 // q term (implicit ea=1)
    #pragma unroll
    for (int off = 16; off; off >>= 1) t += __shfl_down_sync(0xffffffffu, t, off);
    if (lane == 0) atomicAdd(out + dst, t);
}

// ---------------- launch ----------------
extern "C" void kernel_launch(void* const* d_in, const int* in_sizes, int n_in,
                              void* d_out, int out_size) {
    const float* x     = (const float*)d_in[0];
    const void*  ei    = d_in[1];
    const float* ea    = (const float*)d_in[2];
    const float* w_e1  = (const float*)d_in[3];
    const float* b_e1  = (const float*)d_in[4];
    const float* root1 = (const float*)d_in[5];
    const float* bias1 = (const float*)d_in[6];
    const float* w_e2  = (const float*)d_in[7];
    const float* b_e2  = (const float*)d_in[8];
    const float* root2 = (const float*)d_in[9];
    const float* bias2 = (const float*)d_in[10];
    float* out = (float*)d_out;

    k0a_detect<<<1, 32>>>((const int*)ei);
    k0b_convert<<<6250, 256>>>(ei);
    zero_agg_kernel<<<3125, 256>>>();
    k1_mma<<<N_EDGES / 128, 128>>>(x, ea, w_e1, b_e1);
    k2_node<<<(N_NODES + 7) / 8, 256>>>(x, root1, bias1, w_e2, b_e2, root2, bias2, out);
    k3_edge_layer2<<<N_EDGES / 8, 256>>>(ea, out);
}

// round 7
// speedup vs baseline: 1.5945x; 1.2797x over previous
#include <cuda_runtime.h>
#include <cstdint>

#define N_NODES 50000
#define N_EDGES 800000
#define ED 54
#define HID 64

// ---------------- scratch (device globals: allocation-free rule) ----------------
__device__ float g_agg[N_NODES * HID];   // layer-1 aggregation, 12.8 MB
__device__ float g_p[N_NODES * 56];      // p[0..53], q at [54], pad to 56
__device__ int   g_ei[2 * N_EDGES];      // normalized int32 indices
__device__ int   g_idx_is64;             // dtype flag

__device__ __forceinline__ uint32_t f2tf32(float f) {
    uint32_t r;
    asm("cvt.rna.tf32.f32 %0, %1;" : "=r"(r) : "f"(f));
    return r;
}

// ---------------- K0a: detect edge_index dtype ----------------
__global__ void k0a_detect(const int* __restrict__ ei_raw) {
    int lane = threadIdx.x;
    int nz = 0;
    #pragma unroll
    for (int r = 0; r < 2; r++) {
        int i = lane + r * 32;
        if (ei_raw[(2 * i * 9973 % (2 * N_EDGES)) | 1] != 0) nz = 1;
    }
    #pragma unroll
    for (int off = 16; off; off >>= 1) nz |= __shfl_down_sync(0xffffffffu, nz, off);
    if (lane == 0) g_idx_is64 = (nz == 0);
}

// ---------------- K0b: normalize indices (clamped) + zero g_agg ----------------
__global__ void k0b_convert_zero(const void* __restrict__ ei_raw) {
    int i = blockIdx.x * blockDim.x + threadIdx.x;   // 6250*256 = 1.6M exactly
    long long v;
    if (g_idx_is64) v = ((const long long*)ei_raw)[i];
    else            v = ((const int*)ei_raw)[i];
    if (v < 0) v = 0;
    if (v >= N_NODES) v = N_NODES - 1;
    g_ei[i] = (int)v;
    if (i < 800000) {                                 // 800000 float4s = 12.8MB
        float4 z = {0.f, 0.f, 0.f, 0.f};
        reinterpret_cast<float4*>(g_agg)[i] = z;
    }
}

// ---------------- K1: layer-1 edge GEMM via mma.sync tf32 + scatter ----------------
// Per 128-edge tile:  msgs[e,o] = sum_i x_i[e] * (A_raw[e,:] @ B_i[:,o])
//   A_raw[e,k] = ea[e,k] (k<54) | 1 (k==54) | 0 (k==55)   -- staged ONCE
//   B_i[k,o]   = w_e1[k, i*64+o] | b_e1[i*64+o] | 0       -- staged per slice i
// x_i folded into A-fragments at load (row-wise scale, exact).
// 8 warps, each owns m=16 edges x n=64 cols; K=56 = 7 k8-steps per slice.
#define SA_STRIDE 136   // banks (8k+e)%32 -> conflict-free staging + frag loads
#define SB_STRIDE 72    // banks (8k+o)%32 -> conflict-free

__global__ __launch_bounds__(256, 3) void k1_mma(
    const float* __restrict__ x, const float* __restrict__ ea,
    const float* __restrict__ w_e1, const float* __restrict__ b_e1)
{
    __shared__ float    sA[56 * SA_STRIDE];   // 30464 B raw floats [k][e]
    __shared__ uint32_t sB[56 * SB_STRIDE];   // 16128 B tf32 bits  [k][o]
    __shared__ float    sXj[4 * 128];         // 2048 B [i][e]
    __shared__ int      sDst[128];            // 512 B          (total 49152 = 48KB)

    const int tid  = threadIdx.x;
    const int wid  = tid >> 5;
    const int lane = tid & 31;
    const int g    = lane >> 2;     // 0..7
    const int tg   = lane & 3;      // 0..3
    const int wb   = wid * 16;      // warp's edge base within tile
    const int e0   = blockIdx.x * 128;        // 6250*128 = 800000

    // ---- stage A (once): 2 halves of k-rows per edge column ----
    {
        const int e = tid & 127, half = tid >> 7;
        const float2* e2 = reinterpret_cast<const float2*>(ea + (size_t)(e0 + e) * ED);
        if (half == 0) {
            #pragma unroll
            for (int j = 0; j < 14; j++) {           // k = 0..27
                float2 v = e2[j];
                sA[(2 * j) * SA_STRIDE + e] = v.x;
                sA[(2 * j + 1) * SA_STRIDE + e] = v.y;
            }
        } else {
            #pragma unroll
            for (int j = 14; j < 27; j++) {          // k = 28..53
                float2 v = e2[j];
                sA[(2 * j) * SA_STRIDE + e] = v.x;
                sA[(2 * j + 1) * SA_STRIDE + e] = v.y;
            }
            sA[54 * SA_STRIDE + e] = 1.0f;           // bias row
            sA[55 * SA_STRIDE + e] = 0.0f;           // pad row
        }
    }
    if (tid < 128) {
        int src = g_ei[e0 + tid];
        sDst[tid] = g_ei[N_EDGES + e0 + tid];
        float4 xv = *reinterpret_cast<const float4*>(x + (size_t)src * 4);
        sXj[0 * 128 + tid] = xv.x; sXj[1 * 128 + tid] = xv.y;
        sXj[2 * 128 + tid] = xv.z; sXj[3 * 128 + tid] = xv.w;
    }

    float acc[8][4];
    #pragma unroll
    for (int n = 0; n < 8; n++)
        #pragma unroll
        for (int c = 0; c < 4; c++) acc[n][c] = 0.f;

    for (int i = 0; i < 4; i++) {
        __syncthreads();   // prior slice's mma reads done (i=0: A/x staging fencing)
        // ---- stage B slice i ----
        for (int idx = tid; idx < 56 * 64; idx += 256) {
            int k = idx >> 6, o = idx & 63;
            float v = 0.f;
            if (k < 54)       v = w_e1[k * 256 + i * 64 + o];
            else if (k == 54) v = b_e1[i * 64 + o];
            sB[k * SB_STRIDE + o] = f2tf32(v);
        }
        __syncthreads();

        const float xT = sXj[i * 128 + wb + g];
        const float xB = sXj[i * 128 + wb + g + 8];

        #pragma unroll
        for (int kb = 0; kb < 7; kb++) {
            const float* rA0 = sA + (kb * 8 + tg) * SA_STRIDE + wb;
            const float* rA4 = rA0 + 4 * SA_STRIDE;
            const uint32_t* rB0 = sB + (kb * 8 + tg) * SB_STRIDE + g;
            const uint32_t* rB4 = rB0 + 4 * SB_STRIDE;
            uint32_t a0 = f2tf32(rA0[g] * xT);
            uint32_t a1 = f2tf32(rA0[g + 8] * xB);
            uint32_t a2 = f2tf32(rA4[g] * xT);
            uint32_t a3 = f2tf32(rA4[g + 8] * xB);
            #pragma unroll
            for (int n = 0; n < 8; n++) {
                uint32_t b0 = rB0[n * 8], b1 = rB4[n * 8];
                asm volatile(
                    "mma.sync.aligned.m16n8k8.row.col.f32.tf32.tf32.f32 "
                    "{%0,%1,%2,%3}, {%4,%5,%6,%7}, {%8,%9}, {%0,%1,%2,%3};"
                    : "+f"(acc[n][0]), "+f"(acc[n][1]), "+f"(acc[n][2]), "+f"(acc[n][3])
                    : "r"(a0), "r"(a1), "r"(a2), "r"(a3), "r"(b0), "r"(b1));
            }
        }
    }

    // ---- epilogue: c0,c1 -> edge wb+g; c2,c3 -> edge wb+g+8; cols tg*2 + n*8 ----
    int dA = sDst[wb + g], dB = sDst[wb + g + 8];
    float* pA = g_agg + (size_t)dA * HID + tg * 2;
    float* pB = g_agg + (size_t)dB * HID + tg * 2;
    #pragma unroll
    for (int n = 0; n < 8; n++) {
        asm volatile("red.global.add.v2.f32 [%0], {%1,%2};"
                     :: "l"(pA + n * 8), "f"(acc[n][0]), "f"(acc[n][1]) : "memory");
        asm volatile("red.global.add.v2.f32 [%0], {%1,%2};"
                     :: "l"(pB + n * 8), "f"(acc[n][2]), "f"(acc[n][3]) : "memory");
    }
}

// ---------------- K2: node update; h = relu(agg + x@root1 + b1); emit p,q and out-init ----------------
__global__ __launch_bounds__(256) void k2_node(
    const float* __restrict__ x, const float* __restrict__ root1,
    const float* __restrict__ bias1, const float* __restrict__ w_e2,
    const float* __restrict__ b_e2, const float* __restrict__ root2,
    const float* __restrict__ bias2, float* __restrict__ out)
{
    __shared__ float sR1[256], sB1[64], sR2[64];
    __shared__ float sW2[55 * 65];      // row 54 = b_e2; stride 65 -> conflict-free
    __shared__ float sH[8][64];

    const int tid = threadIdx.x;
    for (int idx = tid; idx < 55 * 64; idx += 256) {
        int k = idx >> 6, o = idx & 63;
        sW2[k * 65 + o] = (k < 54) ? w_e2[k * 64 + o] : b_e2[o];
    }
    if (tid < 256) sR1[tid] = root1[tid];
    if (tid < 64) { sB1[tid] = bias1[tid]; sR2[tid] = root2[tid]; }
    __syncthreads();

    const int wid = tid >> 5, lane = tid & 31;
    const int n = blockIdx.x * 8 + wid;
    if (n >= N_NODES) return;

    const float* aggr = g_agg + (size_t)n * HID;
    float x0 = x[n * 4 + 0], x1 = x[n * 4 + 1], x2 = x[n * 4 + 2], x3 = x[n * 4 + 3];
    int l2 = lane + 32;
    float h0 = aggr[lane] + x0 * sR1[lane] + x1 * sR1[64 + lane]
             + x2 * sR1[128 + lane] + x3 * sR1[192 + lane] + sB1[lane];
    float h1 = aggr[l2] + x0 * sR1[l2] + x1 * sR1[64 + l2]
             + x2 * sR1[128 + l2] + x3 * sR1[192 + l2] + sB1[l2];
    h0 = fmaxf(h0, 0.f); h1 = fmaxf(h1, 0.f);
    sH[wid][lane] = h0; sH[wid][l2] = h1;
    __syncwarp();

    float* pn = g_p + (size_t)n * 56;
    {
        float acc = 0.f;
        #pragma unroll
        for (int o = 0; o < 64; o++) acc += sW2[lane * 65 + o] * sH[wid][o];
        pn[lane] = acc;
    }
    if (l2 < 55) {
        float acc = 0.f;
        #pragma unroll
        for (int o = 0; o < 64; o++) acc += sW2[l2 * 65 + o] * sH[wid][o];
        pn[l2] = acc;
    }
    float t = h0 * sR2[lane] + h1 * sR2[l2];
    #pragma unroll
    for (int off = 16; off; off >>= 1) t += __shfl_down_sync(0xffffffffu, t, off);
    if (lane == 0) out[n] = t + bias2[0];
}

// ---------------- K3: layer-2 edges: out[dst] += ea[e].p[src] + q[src] ----------------
__global__ __launch_bounds__(256) void k3_edge_layer2(
    const float* __restrict__ ea, float* __restrict__ out)
{
    const int tid = threadIdx.x, wid = tid >> 5, lane = tid & 31;
    const int e = blockIdx.x * 8 + wid;
    if (e >= N_EDGES) return;
    int src = g_ei[e], dst = g_ei[N_EDGES + e];
    float t = 0.f;
    if (lane < 27) {
        float2 av = reinterpret_cast<const float2*>(ea + (size_t)e * ED)[lane];
        float2 pv = reinterpret_cast<const float2*>(g_p + (size_t)src * 56)[lane];
        t = av.x * pv.x + av.y * pv.y;
    } else if (lane == 27) {
        t = g_p[(size_t)src * 56 + 54];          // q term (implicit ea=1)
    }
    #pragma unroll
    for (int off = 16; off; off >>= 1) t += __shfl_down_sync(0xffffffffu, t, off);
    if (lane == 0) atomicAdd(out + dst, t);
}

// ---------------- launch ----------------
extern "C" void kernel_launch(void* const* d_in, const int* in_sizes, int n_in,
                              void* d_out, int out_size) {
    const float* x     = (const float*)d_in[0];
    const void*  ei    = d_in[1];
    const float* ea    = (const float*)d_in[2];
    const float* w_e1  = (const float*)d_in[3];
    const float* b_e1  = (const float*)d_in[4];
    const float* root1 = (const float*)d_in[5];
    const float* bias1 = (const float*)d_in[6];
    const float* w_e2  = (const float*)d_in[7];
    const float* b_e2  = (const float*)d_in[8];
    const float* root2 = (const float*)d_in[9];
    const float* bias2 = (const float*)d_in[10];
    float* out = (float*)d_out;

    k0a_detect<<<1, 32>>>((const int*)ei);
    k0b_convert_zero<<<6250, 256>>>(ei);
    k1_mma<<<N_EDGES / 128, 256>>>(x, ea, w_e1, b_e1);
    k2_node<<<(N_NODES + 7) / 8, 256>>>(x, root1, bias1, w_e2, b_e2, root2, bias2, out);
    k3_edge_layer2<<<N_EDGES / 8, 256>>>(ea, out);
}